// round 5
// baseline (speedup 1.0000x reference)
#include <cuda_runtime.h>
#include <cstdint>

#define NROWS 32768
#define KCODES 8192
#define DIM 256

#define OFF_ZQ   ((size_t)NROWS * DIM)
#define OFF_IDX  (2u * (size_t)NROWS * DIM)
#define OFF_STATS (2u * (size_t)NROWS * DIM + NROWS)

// ---------------- device scratch (alloc-free) ----------------
__device__ float g_zeT2[(size_t)DIM * NROWS * 2];  // [k][row dup x2]
__device__ float g_embT[(size_t)DIM * KCODES];     // [k][code]
__device__ float g_enorm[KCODES];
__device__ float g_rownorm[NROWS];
__device__ int   g_usage[KCODES];

// ---------------- helpers ----------------
__device__ __forceinline__ void ffma2(unsigned long long& d, unsigned long long a, unsigned long long b) {
    asm("fma.rn.f32x2 %0, %1, %2, %0;" : "+l"(d) : "l"(a), "l"(b));
}
__device__ __forceinline__ void cpa16(unsigned s, const float* g) {
    asm volatile("cp.async.cg.shared.global [%0], [%1], 16;" :: "r"(s), "l"(g));
}
__device__ __forceinline__ float f2lo(unsigned long long u) { return __uint_as_float((unsigned)u); }
__device__ __forceinline__ float f2hi(unsigned long long u) { return __uint_as_float((unsigned)(u >> 32)); }

// ---------------- transpose z_e [NROWS,256] -> dup [256][2*NROWS] ----------------
__global__ void transpose_ze_dup_k(const float* __restrict__ src) {
    __shared__ float tile[32][33];
    int r0 = blockIdx.x * 32, c0 = blockIdx.y * 32;
    int tx = threadIdx.x, ty = threadIdx.y;
#pragma unroll
    for (int i = 0; i < 4; i++) {
        int r = r0 + ty + i * 8;
        tile[ty + i * 8][tx] = src[(size_t)r * DIM + c0 + tx];
    }
    __syncthreads();
    float2* dst = (float2*)g_zeT2;
#pragma unroll
    for (int i = 0; i < 4; i++) {
        int c = c0 + ty + i * 8;
        float v = tile[tx][ty + i * 8];
        dst[(size_t)c * NROWS + r0 + tx] = make_float2(v, v);
    }
}

// ---------------- transpose embedding [KCODES,256] -> [256][KCODES] ----------------
__global__ void transpose_emb_k(const float* __restrict__ src) {
    __shared__ float tile[32][33];
    int r0 = blockIdx.x * 32, c0 = blockIdx.y * 32;
    int tx = threadIdx.x, ty = threadIdx.y;
#pragma unroll
    for (int i = 0; i < 4; i++) {
        int r = r0 + ty + i * 8;
        tile[ty + i * 8][tx] = src[(size_t)r * DIM + c0 + tx];
    }
    __syncthreads();
#pragma unroll
    for (int i = 0; i < 4; i++) {
        int c = c0 + ty + i * 8;
        g_embT[(size_t)c * KCODES + r0 + tx] = tile[tx][ty + i * 8];
    }
}

// ---------------- norms + zero usage ----------------
__global__ void norms_k(const float* __restrict__ ze, const float* __restrict__ emb) {
    int i = blockIdx.x * 256 + threadIdx.x;
    if (i < KCODES) {
        const float4* p = (const float4*)(emb + (size_t)i * DIM);
        float s0 = 0.f, s1 = 0.f, s2 = 0.f, s3 = 0.f;
#pragma unroll 8
        for (int j = 0; j < 64; j++) {
            float4 v = p[j];
            s0 = fmaf(v.x, v.x, s0); s1 = fmaf(v.y, v.y, s1);
            s2 = fmaf(v.z, v.z, s2); s3 = fmaf(v.w, v.w, s3);
        }
        g_enorm[i] = (s0 + s1) + (s2 + s3);
        g_usage[i] = 0;
    }
    if (i < NROWS) {
        const float4* p = (const float4*)(ze + (size_t)i * DIM);
        float s0 = 0.f, s1 = 0.f, s2 = 0.f, s3 = 0.f;
#pragma unroll 8
        for (int j = 0; j < 64; j++) {
            float4 v = p[j];
            s0 = fmaf(v.x, v.x, s0); s1 = fmaf(v.y, v.y, s1);
            s2 = fmaf(v.z, v.z, s2); s3 = fmaf(v.w, v.w, s3);
        }
        g_rownorm[i] = (s0 + s1) + (s2 + s3);
    }
}

// ---------------- main fused GEMM + argmin + gather ----------------
#define TM 128
#define TN 128
#define KC 16
#define NT (KCODES / TN)      // 64 code tiles
#define NSTAGE (NT * 16)      // 1024 k-chunk stages

__global__ void __launch_bounds__(256, 2)
vq_main_k(const float* __restrict__ emb, const float* __restrict__ ze,
          float* __restrict__ out) {
    // As holds duplicated rows: [KC][2*TM] floats; Bs: [KC][TN]. Total exactly 48KB.
    __shared__ __align__(16) float As[2][KC][TM * 2];
    __shared__ __align__(16) float Bs[2][KC][TN];

    const int tid = threadIdx.x;
    const int tx = tid & 15, ty = tid >> 4;
    const int rbase = blockIdx.x * TM;

    // B loader mapping: 512 float4 per tile, 2 per thread
    const int bl0 = tid, bl1 = tid + 256;
    const int bk0 = bl0 >> 5, bs0 = (bl0 & 31) << 2;
    const int bk1 = bl1 >> 5, bs1 = (bl1 & 31) << 2;

    const unsigned sa_base = (unsigned)__cvta_generic_to_shared(&As[0][0][0]);
    const unsigned sb_base = (unsigned)__cvta_generic_to_shared(&Bs[0][0][0]);
    const unsigned bo0 = (unsigned)((bk0 * TN + bs0) * 4);
    const unsigned bo1 = (unsigned)((bk1 * TN + bs1) * 4);

    const float* gA = g_zeT2 + (size_t)rbase * 2;  // [k][rowdup] stride 2*NROWS
    const float* gB = g_embT;                      // [k][code] stride KCODES

    float bestd[8];
    int   besti[8];
#pragma unroll
    for (int i = 0; i < 8; i++) { bestd[i] = 3.4e38f; besti[i] = 0; }

    // preload row norms (rows fixed per thread across all code tiles)
    float rn[8];
#pragma unroll
    for (int i = 0; i < 8; i++) {
        const int row = (i < 4) ? (ty << 2) + i : 64 + (ty << 2) + (i - 4);
        rn[i] = g_rownorm[rbase + row];
    }

    auto issue = [&](int s, int b) {
        const int k0 = (s & 15) << 4;
        const int cb = (s >> 4) << 7;
        const float* pa = gA + (size_t)k0 * (2 * NROWS);
        const float* pb = gB + (size_t)k0 * KCODES + cb;
        const unsigned ab = sa_base + (unsigned)b * (KC * TM * 2 * 4);
        const unsigned bb = sb_base + (unsigned)b * (KC * TN * 4);
        // A: 1024 float4, 4 per thread
#pragma unroll
        for (int j = 0; j < 4; j++) {
            const int lin = tid + j * 256;
            const int ak = lin >> 6, as = (lin & 63) << 2;
            cpa16(ab + (unsigned)((ak * TM * 2 + as) * 4),
                  pa + (size_t)ak * (2 * NROWS) + as);
        }
        cpa16(bb + bo0, pb + (size_t)bk0 * KCODES + bs0);
        cpa16(bb + bo1, pb + (size_t)bk1 * KCODES + bs1);
    };

    issue(0, 0);
    asm volatile("cp.async.commit_group;" ::: "memory");
    int buf = 0;

#pragma unroll 1
    for (int nt = 0; nt < NT; nt++) {
        unsigned long long acc[32];
#pragma unroll
        for (int i = 0; i < 32; i++) acc[i] = 0ull;

#pragma unroll 1
        for (int ks = 0; ks < 16; ks++) {
            const int s = (nt << 4) + ks;
            if (s + 1 < NSTAGE) issue(s + 1, buf ^ 1);
            asm volatile("cp.async.commit_group;" ::: "memory");
            asm volatile("cp.async.wait_group 1;" ::: "memory");
            __syncthreads();
#pragma unroll
            for (int k = 0; k < KC; k++) {
                // duplicated A: each ulonglong is a packed (a,a) pair
                const ulonglong2 a01 = *(const ulonglong2*)&As[buf][k][(ty << 3)];
                const ulonglong2 a23 = *(const ulonglong2*)&As[buf][k][(ty << 3) + 4];
                const ulonglong2 a45 = *(const ulonglong2*)&As[buf][k][128 + (ty << 3)];
                const ulonglong2 a67 = *(const ulonglong2*)&As[buf][k][128 + (ty << 3) + 4];
                const ulonglong2 b0 = *(const ulonglong2*)&Bs[buf][k][(tx << 2)];
                const ulonglong2 b1 = *(const ulonglong2*)&Bs[buf][k][64 + (tx << 2)];
                ffma2(acc[0],  a01.x, b0.x); ffma2(acc[1],  a01.x, b0.y);
                ffma2(acc[2],  a01.x, b1.x); ffma2(acc[3],  a01.x, b1.y);
                ffma2(acc[4],  a01.y, b0.x); ffma2(acc[5],  a01.y, b0.y);
                ffma2(acc[6],  a01.y, b1.x); ffma2(acc[7],  a01.y, b1.y);
                ffma2(acc[8],  a23.x, b0.x); ffma2(acc[9],  a23.x, b0.y);
                ffma2(acc[10], a23.x, b1.x); ffma2(acc[11], a23.x, b1.y);
                ffma2(acc[12], a23.y, b0.x); ffma2(acc[13], a23.y, b0.y);
                ffma2(acc[14], a23.y, b1.x); ffma2(acc[15], a23.y, b1.y);
                ffma2(acc[16], a45.x, b0.x); ffma2(acc[17], a45.x, b0.y);
                ffma2(acc[18], a45.x, b1.x); ffma2(acc[19], a45.x, b1.y);
                ffma2(acc[20], a45.y, b0.x); ffma2(acc[21], a45.y, b0.y);
                ffma2(acc[22], a45.y, b1.x); ffma2(acc[23], a45.y, b1.y);
                ffma2(acc[24], a67.x, b0.x); ffma2(acc[25], a67.x, b0.y);
                ffma2(acc[26], a67.x, b1.x); ffma2(acc[27], a67.x, b1.y);
                ffma2(acc[28], a67.y, b0.x); ffma2(acc[29], a67.y, b0.y);
                ffma2(acc[30], a67.y, b1.x); ffma2(acc[31], a67.y, b1.y);
            }
            __syncthreads();
            buf ^= 1;
        }

        // epilogue for this code tile: d = (||x||^2 - 2 s) + ||e||^2 (jax op order)
        {
            const int cb = nt << 7;
            const float4 e0 = *(const float4*)&g_enorm[cb + (tx << 2)];
            const float4 e1 = *(const float4*)&g_enorm[cb + 64 + (tx << 2)];
            const float en[8] = {e0.x, e0.y, e0.z, e0.w, e1.x, e1.y, e1.z, e1.w};
            const int c0 = cb + (tx << 2);
            const int cidx[8] = {c0, c0 + 1, c0 + 2, c0 + 3, c0 + 64, c0 + 65, c0 + 66, c0 + 67};
#pragma unroll
            for (int i = 0; i < 8; i++) {
                const float x2 = rn[i];
#pragma unroll
                for (int j = 0; j < 4; j++) {
                    const unsigned long long u = acc[i * 4 + j];
                    const float d0 = (x2 - 2.0f * f2lo(u)) + en[j * 2];
                    const float d1 = (x2 - 2.0f * f2hi(u)) + en[j * 2 + 1];
                    if (d0 < bestd[i]) { bestd[i] = d0; besti[i] = cidx[j * 2]; }
                    if (d1 < bestd[i]) { bestd[i] = d1; besti[i] = cidx[j * 2 + 1]; }
                }
            }
        }
    }

    // cross-thread argmin reduction (reuse smem tiles as scratch)
    // rv: 2048 floats in As (32KB region). ri: first 8192B of Bs.
    // s_idx: next 512B of Bs (byte offsets 8192..8703 < 16384) -- in bounds.
    float* rv = (float*)&As[0][0][0];
    int*   ri = (int*)&Bs[0][0][0];
    int*   s_idx = ((int*)&Bs[0][0][0]) + 2048;
#pragma unroll
    for (int i = 0; i < 8; i++) {
        const int row = (i < 4) ? (ty << 2) + i : 64 + (ty << 2) + (i - 4);
        rv[row * 16 + tx] = bestd[i];
        ri[row * 16 + tx] = besti[i];
    }
    __syncthreads();
    if (tid < TM) {
        const int row = tid;
        float bv = rv[row * 16];
        int   bi = ri[row * 16];
#pragma unroll
        for (int t = 1; t < 16; t++) {
            const float v = rv[row * 16 + t];
            const int   ix = ri[row * 16 + t];
            if (v < bv || (v == bv && ix < bi)) { bv = v; bi = ix; }
        }
        s_idx[row] = bi;
        out[OFF_IDX + rbase + row] = (float)bi;
        atomicAdd(&g_usage[bi], 1);
    }
    __syncthreads();

    // gather z_q; z_q_st = z_e + (z_q - z_e) computed exactly as the reference
    {
        const int row = tid >> 1, half = tid & 1;
        const int code = s_idx[row];
        const float4* src = (const float4*)(emb + (size_t)code * DIM + half * 128);
        const float4* sze = (const float4*)(ze + (size_t)(rbase + row) * DIM + half * 128);
        float4* d1 = (float4*)(out + (size_t)(rbase + row) * DIM + half * 128);
        float4* d2 = (float4*)(out + OFF_ZQ + (size_t)(rbase + row) * DIM + half * 128);
#pragma unroll
        for (int q = 0; q < 32; q++) {
            const float4 v = src[q];
            const float4 x = sze[q];
            float4 st;
            st.x = x.x + (v.x - x.x);
            st.y = x.y + (v.y - x.y);
            st.z = x.z + (v.z - x.z);
            st.w = x.w + (v.w - x.w);
            d1[q] = st;
            d2[q] = v;
        }
    }
}

// ---------------- stats ----------------
__global__ void stats_k(float* __restrict__ out) {
    __shared__ float se[256];
    __shared__ int   sd[256];
    const int t = threadIdx.x;
    float ent = 0.f;
    int dead = 0;
    for (int c = t; c < KCODES; c += 256) {
        const int u = g_usage[c];
        if (u == 0) dead++;
        else {
            const float p = (float)u * (1.0f / (float)NROWS);
            ent -= p * logf(p);
        }
    }
    se[t] = ent; sd[t] = dead;
    __syncthreads();
    for (int off = 128; off > 0; off >>= 1) {
        if (t < off) { se[t] += se[t + off]; sd[t] += sd[t + off]; }
        __syncthreads();
    }
    if (t == 0) {
        out[OFF_STATS]     = expf(se[0]);
        out[OFF_STATS + 1] = (float)sd[0] * (1.0f / (float)KCODES);
    }
}

// ---------------- launch ----------------
extern "C" void kernel_launch(void* const* d_in, const int* in_sizes, int n_in,
                              void* d_out, int out_size) {
    const float* z_e = (const float*)d_in[0];
    const float* emb = (const float*)d_in[1];
    if (n_in >= 2 && in_sizes[0] == KCODES * DIM && in_sizes[1] == NROWS * DIM) {
        const float* t = z_e; z_e = emb; emb = t;  // defensive input-order swap
    }
    float* out = (float*)d_out;

    transpose_ze_dup_k<<<dim3(NROWS / 32, DIM / 32), dim3(32, 8)>>>(z_e);
    transpose_emb_k<<<dim3(KCODES / 32, DIM / 32), dim3(32, 8)>>>(emb);
    norms_k<<<NROWS / 256, 256>>>(z_e, emb);
    vq_main_k<<<NROWS / TM, 256>>>(emb, z_e, out);
    stats_k<<<1, 256>>>(out);
}

// round 7
// speedup vs baseline: 1.1609x; 1.1609x over previous
#include <cuda_runtime.h>
#include <cstdint>

#define NROWS 32768
#define KCODES 8192
#define DIM 256

#define OFF_ZQ   ((size_t)NROWS * DIM)
#define OFF_IDX  (2u * (size_t)NROWS * DIM)
#define OFF_STATS (2u * (size_t)NROWS * DIM + NROWS)

// ---------------- device scratch (alloc-free) ----------------
__device__ float g_zeT[(size_t)DIM * NROWS];    // [k][row]
__device__ float g_embT[(size_t)DIM * KCODES];  // [k][code]
__device__ float g_enorm[KCODES];
__device__ float g_rownorm[NROWS];
__device__ int   g_usage[KCODES];

// ---------------- helpers ----------------
__device__ __forceinline__ unsigned long long pk2(float a) {
    unsigned long long r;
    asm("mov.b64 %0, {%1, %1};" : "=l"(r) : "f"(a));
    return r;
}
__device__ __forceinline__ void ffma2(unsigned long long& d, unsigned long long a, unsigned long long b) {
    asm("fma.rn.f32x2 %0, %1, %2, %0;" : "+l"(d) : "l"(a), "l"(b));
}
__device__ __forceinline__ void cpa16(unsigned s, const float* g) {
    asm volatile("cp.async.cg.shared.global [%0], [%1], 16;" :: "r"(s), "l"(g));
}
__device__ __forceinline__ float f2lo(unsigned long long u) { return __uint_as_float((unsigned)u); }
__device__ __forceinline__ float f2hi(unsigned long long u) { return __uint_as_float((unsigned)(u >> 32)); }

// ---------------- transpose [ROWS,256] -> [256,ROWS] ----------------
template<int ROWS, bool TO_EMB>
__global__ void transpose256_k(const float* __restrict__ src) {
    __shared__ float tile[32][33];
    float* dst = TO_EMB ? g_embT : g_zeT;
    int r0 = blockIdx.x * 32, c0 = blockIdx.y * 32;
    int tx = threadIdx.x, ty = threadIdx.y;
#pragma unroll
    for (int i = 0; i < 4; i++) {
        int r = r0 + ty + i * 8;
        tile[ty + i * 8][tx] = src[(size_t)r * DIM + c0 + tx];
    }
    __syncthreads();
#pragma unroll
    for (int i = 0; i < 4; i++) {
        int c = c0 + ty + i * 8;
        dst[(size_t)c * ROWS + r0 + tx] = tile[tx][ty + i * 8];
    }
}

// ---------------- norms + zero usage ----------------
__global__ void norms_k(const float* __restrict__ ze, const float* __restrict__ emb) {
    int i = blockIdx.x * 256 + threadIdx.x;
    if (i < KCODES) {
        const float4* p = (const float4*)(emb + (size_t)i * DIM);
        float s0 = 0.f, s1 = 0.f, s2 = 0.f, s3 = 0.f;
#pragma unroll 8
        for (int j = 0; j < 64; j++) {
            float4 v = p[j];
            s0 = fmaf(v.x, v.x, s0); s1 = fmaf(v.y, v.y, s1);
            s2 = fmaf(v.z, v.z, s2); s3 = fmaf(v.w, v.w, s3);
        }
        g_enorm[i] = (s0 + s1) + (s2 + s3);
        g_usage[i] = 0;
    }
    if (i < NROWS) {
        const float4* p = (const float4*)(ze + (size_t)i * DIM);
        float s0 = 0.f, s1 = 0.f, s2 = 0.f, s3 = 0.f;
#pragma unroll 8
        for (int j = 0; j < 64; j++) {
            float4 v = p[j];
            s0 = fmaf(v.x, v.x, s0); s1 = fmaf(v.y, v.y, s1);
            s2 = fmaf(v.z, v.z, s2); s3 = fmaf(v.w, v.w, s3);
        }
        g_rownorm[i] = (s0 + s1) + (s2 + s3);
    }
}

// ---------------- main fused GEMM + argmin + gather ----------------
#define TM 128
#define TN 128
#define KC 16
#define NSTG 3
#define NT (KCODES / TN)      // 64 code tiles
#define NSTAGE (NT * 16)      // 1024 k-chunk stages

__global__ void __launch_bounds__(256, 2)
vq_main_k(const float* __restrict__ emb, const float* __restrict__ ze,
          float* __restrict__ out) {
    // 3-stage ring: As 24KB + Bs 24KB = 48KB exactly.
    __shared__ __align__(16) float As[NSTG][KC][TM];
    __shared__ __align__(16) float Bs[NSTG][KC][TN];

    const int tid = threadIdx.x;
    const int tx = tid & 15, ty = tid >> 4;
    const int rbase = blockIdx.x * TM;

    // loader mapping: 512 float4 per operand tile, 2 per thread
    const int lin0 = tid, lin1 = tid + 256;
    const int ak0 = lin0 >> 5, as0 = (lin0 & 31) << 2;
    const int ak1 = lin1 >> 5, as1 = (lin1 & 31) << 2;

    const unsigned sa_base = (unsigned)__cvta_generic_to_shared(&As[0][0][0]);
    const unsigned sb_base = (unsigned)__cvta_generic_to_shared(&Bs[0][0][0]);
    const unsigned o0 = (unsigned)((ak0 * TM + as0) * 4);
    const unsigned o1 = (unsigned)((ak1 * TM + as1) * 4);

    const float* gA = g_zeT + rbase;  // [k][row] stride NROWS
    const float* gB = g_embT;         // [k][code] stride KCODES

    float bestd[8];
    int   besti[8];
#pragma unroll
    for (int i = 0; i < 8; i++) { bestd[i] = 3.4e38f; besti[i] = 0; }

    // preload row norms (rows fixed per thread across all code tiles)
    float rn[8];
#pragma unroll
    for (int i = 0; i < 8; i++) {
        const int row = (i < 4) ? (ty << 2) + i : 64 + (ty << 2) + (i - 4);
        rn[i] = g_rownorm[rbase + row];
    }

    auto issue = [&](int s) {
        const int b = s % NSTG;
        const int k0 = (s & 15) << 4;
        const int cb = (s >> 4) << 7;
        const float* pa = gA + (size_t)k0 * NROWS;
        const float* pb = gB + (size_t)k0 * KCODES + cb;
        const unsigned ab = sa_base + (unsigned)b * (KC * TM * 4);
        const unsigned bb = sb_base + (unsigned)b * (KC * TN * 4);
        cpa16(ab + o0, pa + (size_t)ak0 * NROWS + as0);
        cpa16(ab + o1, pa + (size_t)ak1 * NROWS + as1);
        cpa16(bb + o0, pb + (size_t)ak0 * KCODES + as0);
        cpa16(bb + o1, pb + (size_t)ak1 * KCODES + as1);
    };

    // prologue: 2 stages in flight
    issue(0);
    asm volatile("cp.async.commit_group;" ::: "memory");
    issue(1);
    asm volatile("cp.async.commit_group;" ::: "memory");

#pragma unroll 1
    for (int nt = 0; nt < NT; nt++) {
        unsigned long long acc[32];
#pragma unroll
        for (int i = 0; i < 32; i++) acc[i] = 0ull;

#pragma unroll 1
        for (int ks = 0; ks < 16; ks++) {
            const int s = (nt << 4) + ks;
            // stage s arrived when <=1 groups pending (s, s+1 in flight)
            asm volatile("cp.async.wait_group 1;" ::: "memory");
            __syncthreads();   // publish stage s; also frees buffer (s+2)%3
            if (s + 2 < NSTAGE) issue(s + 2);
            asm volatile("cp.async.commit_group;" ::: "memory");

            const int buf = s % NSTG;
#pragma unroll
            for (int k = 0; k < KC; k++) {
                const float4 a0 = *(const float4*)&As[buf][k][(ty << 2)];
                const float4 a1 = *(const float4*)&As[buf][k][64 + (ty << 2)];
                const ulonglong2 b0 = *(const ulonglong2*)&Bs[buf][k][(tx << 2)];
                const ulonglong2 b1 = *(const ulonglong2*)&Bs[buf][k][64 + (tx << 2)];
                unsigned long long av;
                av = pk2(a0.x);
                ffma2(acc[0], av, b0.x);  ffma2(acc[1], av, b0.y);
                ffma2(acc[2], av, b1.x);  ffma2(acc[3], av, b1.y);
                av = pk2(a0.y);
                ffma2(acc[4], av, b0.x);  ffma2(acc[5], av, b0.y);
                ffma2(acc[6], av, b1.x);  ffma2(acc[7], av, b1.y);
                av = pk2(a0.z);
                ffma2(acc[8], av, b0.x);  ffma2(acc[9], av, b0.y);
                ffma2(acc[10], av, b1.x); ffma2(acc[11], av, b1.y);
                av = pk2(a0.w);
                ffma2(acc[12], av, b0.x); ffma2(acc[13], av, b0.y);
                ffma2(acc[14], av, b1.x); ffma2(acc[15], av, b1.y);
                av = pk2(a1.x);
                ffma2(acc[16], av, b0.x); ffma2(acc[17], av, b0.y);
                ffma2(acc[18], av, b1.x); ffma2(acc[19], av, b1.y);
                av = pk2(a1.y);
                ffma2(acc[20], av, b0.x); ffma2(acc[21], av, b0.y);
                ffma2(acc[22], av, b1.x); ffma2(acc[23], av, b1.y);
                av = pk2(a1.z);
                ffma2(acc[24], av, b0.x); ffma2(acc[25], av, b0.y);
                ffma2(acc[26], av, b1.x); ffma2(acc[27], av, b1.y);
                av = pk2(a1.w);
                ffma2(acc[28], av, b0.x); ffma2(acc[29], av, b0.y);
                ffma2(acc[30], av, b1.x); ffma2(acc[31], av, b1.y);
            }
            // no trailing barrier: next stage's top barrier protects reuse
        }

        // epilogue for this code tile (register-local, barrier-free)
        {
            const int cb = nt << 7;
            const float4 e0 = *(const float4*)&g_enorm[cb + (tx << 2)];
            const float4 e1 = *(const float4*)&g_enorm[cb + 64 + (tx << 2)];
            const float en[8] = {e0.x, e0.y, e0.z, e0.w, e1.x, e1.y, e1.z, e1.w};
            const int c0 = cb + (tx << 2);
            const int cidx[8] = {c0, c0 + 1, c0 + 2, c0 + 3, c0 + 64, c0 + 65, c0 + 66, c0 + 67};
#pragma unroll
            for (int i = 0; i < 8; i++) {
                const float x2 = rn[i];
#pragma unroll
                for (int j = 0; j < 4; j++) {
                    const unsigned long long u = acc[i * 4 + j];
                    const float d0 = (x2 - 2.0f * f2lo(u)) + en[j * 2];
                    const float d1 = (x2 - 2.0f * f2hi(u)) + en[j * 2 + 1];
                    if (d0 < bestd[i]) { bestd[i] = d0; besti[i] = cidx[j * 2]; }
                    if (d1 < bestd[i]) { bestd[i] = d1; besti[i] = cidx[j * 2 + 1]; }
                }
            }
        }
    }

    // cross-thread argmin reduction (reuse smem tiles as scratch)
    // rv: 8KB into As (24KB). ri: 8KB into Bs. s_idx: bytes 8192..8703 of Bs.
    float* rv = (float*)&As[0][0][0];
    int*   ri = (int*)&Bs[0][0][0];
    int*   s_idx = ((int*)&Bs[0][0][0]) + 2048;
    __syncthreads();  // all compute done before scratch overwrite
#pragma unroll
    for (int i = 0; i < 8; i++) {
        const int row = (i < 4) ? (ty << 2) + i : 64 + (ty << 2) + (i - 4);
        rv[row * 16 + tx] = bestd[i];
        ri[row * 16 + tx] = besti[i];
    }
    __syncthreads();
    if (tid < TM) {
        const int row = tid;
        float bv = rv[row * 16];
        int   bi = ri[row * 16];
#pragma unroll
        for (int t = 1; t < 16; t++) {
            const float v = rv[row * 16 + t];
            const int   ix = ri[row * 16 + t];
            if (v < bv || (v == bv && ix < bi)) { bv = v; bi = ix; }
        }
        s_idx[row] = bi;
        out[OFF_IDX + rbase + row] = (float)bi;
        atomicAdd(&g_usage[bi], 1);
    }
    __syncthreads();

    // gather z_q; z_q_st = z_e + (z_q - z_e) as in the reference
    {
        const int row = tid >> 1, half = tid & 1;
        const int code = s_idx[row];
        const float4* src = (const float4*)(emb + (size_t)code * DIM + half * 128);
        const float4* sze = (const float4*)(ze + (size_t)(rbase + row) * DIM + half * 128);
        float4* d1 = (float4*)(out + (size_t)(rbase + row) * DIM + half * 128);
        float4* d2 = (float4*)(out + OFF_ZQ + (size_t)(rbase + row) * DIM + half * 128);
#pragma unroll
        for (int q = 0; q < 32; q++) {
            const float4 v = src[q];
            const float4 x = sze[q];
            float4 st;
            st.x = x.x + (v.x - x.x);
            st.y = x.y + (v.y - x.y);
            st.z = x.z + (v.z - x.z);
            st.w = x.w + (v.w - x.w);
            d1[q] = st;
            d2[q] = v;
        }
    }
}

// ---------------- stats ----------------
__global__ void stats_k(float* __restrict__ out) {
    __shared__ float se[256];
    __shared__ int   sd[256];
    const int t = threadIdx.x;
    float ent = 0.f;
    int dead = 0;
    for (int c = t; c < KCODES; c += 256) {
        const int u = g_usage[c];
        if (u == 0) dead++;
        else {
            const float p = (float)u * (1.0f / (float)NROWS);
            ent -= p * logf(p);
        }
    }
    se[t] = ent; sd[t] = dead;
    __syncthreads();
    for (int off = 128; off > 0; off >>= 1) {
        if (t < off) { se[t] += se[t + off]; sd[t] += sd[t + off]; }
        __syncthreads();
    }
    if (t == 0) {
        out[OFF_STATS]     = expf(se[0]);
        out[OFF_STATS + 1] = (float)sd[0] * (1.0f / (float)KCODES);
    }
}

// ---------------- launch ----------------
extern "C" void kernel_launch(void* const* d_in, const int* in_sizes, int n_in,
                              void* d_out, int out_size) {
    const float* z_e = (const float*)d_in[0];
    const float* emb = (const float*)d_in[1];
    if (n_in >= 2 && in_sizes[0] == KCODES * DIM && in_sizes[1] == NROWS * DIM) {
        const float* t = z_e; z_e = emb; emb = t;  // defensive input-order swap
    }
    float* out = (float*)d_out;

    transpose256_k<NROWS, false><<<dim3(NROWS / 32, DIM / 32), dim3(32, 8)>>>(z_e);
    transpose256_k<KCODES, true><<<dim3(KCODES / 32, DIM / 32), dim3(32, 8)>>>(emb);
    norms_k<<<NROWS / 256, 256>>>(z_e, emb);
    vq_main_k<<<NROWS / TM, 256>>>(emb, z_e, out);
    stats_k<<<1, 256>>>(out);
}

// round 11
// speedup vs baseline: 1.3327x; 1.1481x over previous
#include <cuda_runtime.h>
#include <cstdint>

#define NROWS 32768
#define KCODES 8192
#define DIM 256

#define OFF_ZQ   ((size_t)NROWS * DIM)
#define OFF_IDX  (2u * (size_t)NROWS * DIM)
#define OFF_STATS (2u * (size_t)NROWS * DIM + NROWS)

// ---------------- device scratch (alloc-free) ----------------
__device__ float g_zeT[(size_t)DIM * NROWS];    // [k][row]
__device__ float g_embT[(size_t)DIM * KCODES];  // [k][code]
__device__ float g_enorm[KCODES];
__device__ float g_rownorm[NROWS];
__device__ unsigned long long g_best[NROWS];    // (sortkey(dist)<<32) | code
__device__ int   g_usage[KCODES];

// ---------------- helpers ----------------
__device__ __forceinline__ unsigned long long pk2(float a) {
    unsigned long long r;
    asm("mov.b64 %0, {%1, %1};" : "=l"(r) : "f"(a));
    return r;
}
__device__ __forceinline__ void ffma2(unsigned long long& d, unsigned long long a, unsigned long long b) {
    asm("fma.rn.f32x2 %0, %1, %2, %0;" : "+l"(d) : "l"(a), "l"(b));
}
__device__ __forceinline__ void cpa16(unsigned s, const float* g) {
    asm volatile("cp.async.cg.shared.global [%0], [%1], 16;" :: "r"(s), "l"(g));
}
__device__ __forceinline__ float f2lo(unsigned long long u) { return __uint_as_float((unsigned)u); }
__device__ __forceinline__ float f2hi(unsigned long long u) { return __uint_as_float((unsigned)(u >> 32)); }
// total-order monotonic key for fp32 (handles negatives from rounding)
__device__ __forceinline__ unsigned sortkey(float d) {
    unsigned u = __float_as_uint(d);
    return u ^ (unsigned)(((int)u >> 31) | 0x80000000);
}

// ---------------- transpose [ROWS,256] -> [256,ROWS] ----------------
template<int ROWS, bool TO_EMB>
__global__ void transpose256_k(const float* __restrict__ src) {
    __shared__ float tile[32][33];
    float* dst = TO_EMB ? g_embT : g_zeT;
    int r0 = blockIdx.x * 32, c0 = blockIdx.y * 32;
    int tx = threadIdx.x, ty = threadIdx.y;
#pragma unroll
    for (int i = 0; i < 4; i++) {
        int r = r0 + ty + i * 8;
        tile[ty + i * 8][tx] = src[(size_t)r * DIM + c0 + tx];
    }
    __syncthreads();
#pragma unroll
    for (int i = 0; i < 4; i++) {
        int c = c0 + ty + i * 8;
        dst[(size_t)c * ROWS + r0 + tx] = tile[tx][ty + i * 8];
    }
}

// ---------------- norms + init best/usage ----------------
__global__ void norms_k(const float* __restrict__ ze, const float* __restrict__ emb) {
    int i = blockIdx.x * 256 + threadIdx.x;
    if (i < KCODES) {
        const float4* p = (const float4*)(emb + (size_t)i * DIM);
        float s0 = 0.f, s1 = 0.f, s2 = 0.f, s3 = 0.f;
#pragma unroll 8
        for (int j = 0; j < 64; j++) {
            float4 v = p[j];
            s0 = fmaf(v.x, v.x, s0); s1 = fmaf(v.y, v.y, s1);
            s2 = fmaf(v.z, v.z, s2); s3 = fmaf(v.w, v.w, s3);
        }
        g_enorm[i] = (s0 + s1) + (s2 + s3);
        g_usage[i] = 0;
    }
    if (i < NROWS) {
        const float4* p = (const float4*)(ze + (size_t)i * DIM);
        float s0 = 0.f, s1 = 0.f, s2 = 0.f, s3 = 0.f;
#pragma unroll 8
        for (int j = 0; j < 64; j++) {
            float4 v = p[j];
            s0 = fmaf(v.x, v.x, s0); s1 = fmaf(v.y, v.y, s1);
            s2 = fmaf(v.z, v.z, s2); s3 = fmaf(v.w, v.w, s3);
        }
        g_rownorm[i] = (s0 + s1) + (s2 + s3);
        g_best[i] = 0xFFFFFFFFFFFFFFFFull;
    }
}

// ---------------- main fused GEMM + partial argmin ----------------
// grid = 2048: bid = rt*8 + ct; rt in [0,256): 128-row tile; ct in [0,8): 1024-code chunk.
#define TM 128
#define TN 128
#define KC 16
#define NSTG 3
#define NTL 8                 // code tiles per CTA (8*128 = 1024 codes)
#define NSTAGE_L (NTL * 16)   // 128 k-chunk stages per CTA

__global__ void __launch_bounds__(256, 2)
vq_main_k(float* __restrict__ out) {
    __shared__ __align__(16) float As[NSTG][KC][TM];
    __shared__ __align__(16) float Bs[NSTG][KC][TN];

    const int tid = threadIdx.x;
    const int tx = tid & 15, ty = tid >> 4;
    const int rbase = (blockIdx.x >> 3) * TM;
    const int cbase = (blockIdx.x & 7) * (NTL * TN);

    const int lin0 = tid, lin1 = tid + 256;
    const int ak0 = lin0 >> 5, as0 = (lin0 & 31) << 2;
    const int ak1 = lin1 >> 5, as1 = (lin1 & 31) << 2;

    const unsigned sa_base = (unsigned)__cvta_generic_to_shared(&As[0][0][0]);
    const unsigned sb_base = (unsigned)__cvta_generic_to_shared(&Bs[0][0][0]);
    const unsigned o0 = (unsigned)((ak0 * TM + as0) * 4);
    const unsigned o1 = (unsigned)((ak1 * TM + as1) * 4);

    const float* gA = g_zeT + rbase;          // [k][row] stride NROWS
    const float* gB = g_embT + cbase;         // [k][code] stride KCODES

    float bestd[8];
    int   besti[8];
#pragma unroll
    for (int i = 0; i < 8; i++) { bestd[i] = 3.4e38f; besti[i] = 0; }

    float rn[8];
#pragma unroll
    for (int i = 0; i < 8; i++) {
        const int row = (i < 4) ? (ty << 2) + i : 64 + (ty << 2) + (i - 4);
        rn[i] = g_rownorm[rbase + row];
    }

    auto issue = [&](int s) {
        const int b = s % NSTG;
        const int k0 = (s & 15) << 4;
        const int cb = (s >> 4) << 7;
        const float* pa = gA + (size_t)k0 * NROWS;
        const float* pb = gB + (size_t)k0 * KCODES + cb;
        const unsigned ab = sa_base + (unsigned)b * (KC * TM * 4);
        const unsigned bb = sb_base + (unsigned)b * (KC * TN * 4);
        cpa16(ab + o0, pa + (size_t)ak0 * NROWS + as0);
        cpa16(ab + o1, pa + (size_t)ak1 * NROWS + as1);
        cpa16(bb + o0, pb + (size_t)ak0 * KCODES + as0);
        cpa16(bb + o1, pb + (size_t)ak1 * KCODES + as1);
    };

    issue(0);
    asm volatile("cp.async.commit_group;" ::: "memory");
    issue(1);
    asm volatile("cp.async.commit_group;" ::: "memory");

#pragma unroll 1
    for (int nt = 0; nt < NTL; nt++) {
        unsigned long long acc[32];
#pragma unroll
        for (int i = 0; i < 32; i++) acc[i] = 0ull;

#pragma unroll 1
        for (int ks = 0; ks < 16; ks++) {
            const int s = (nt << 4) + ks;
            asm volatile("cp.async.wait_group 1;" ::: "memory");
            __syncthreads();
            if (s + 2 < NSTAGE_L) issue(s + 2);
            asm volatile("cp.async.commit_group;" ::: "memory");

            const int buf = s % NSTG;
#pragma unroll
            for (int k = 0; k < KC; k++) {
                const float4 a0 = *(const float4*)&As[buf][k][(ty << 2)];
                const float4 a1 = *(const float4*)&As[buf][k][64 + (ty << 2)];
                const ulonglong2 b0 = *(const ulonglong2*)&Bs[buf][k][(tx << 2)];
                const ulonglong2 b1 = *(const ulonglong2*)&Bs[buf][k][64 + (tx << 2)];
                unsigned long long av;
                av = pk2(a0.x);
                ffma2(acc[0], av, b0.x);  ffma2(acc[1], av, b0.y);
                ffma2(acc[2], av, b1.x);  ffma2(acc[3], av, b1.y);
                av = pk2(a0.y);
                ffma2(acc[4], av, b0.x);  ffma2(acc[5], av, b0.y);
                ffma2(acc[6], av, b1.x);  ffma2(acc[7], av, b1.y);
                av = pk2(a0.z);
                ffma2(acc[8], av, b0.x);  ffma2(acc[9], av, b0.y);
                ffma2(acc[10], av, b1.x); ffma2(acc[11], av, b1.y);
                av = pk2(a0.w);
                ffma2(acc[12], av, b0.x); ffma2(acc[13], av, b0.y);
                ffma2(acc[14], av, b1.x); ffma2(acc[15], av, b1.y);
                av = pk2(a1.x);
                ffma2(acc[16], av, b0.x); ffma2(acc[17], av, b0.y);
                ffma2(acc[18], av, b1.x); ffma2(acc[19], av, b1.y);
                av = pk2(a1.y);
                ffma2(acc[20], av, b0.x); ffma2(acc[21], av, b0.y);
                ffma2(acc[22], av, b1.x); ffma2(acc[23], av, b1.y);
                av = pk2(a1.z);
                ffma2(acc[24], av, b0.x); ffma2(acc[25], av, b0.y);
                ffma2(acc[26], av, b1.x); ffma2(acc[27], av, b1.y);
                av = pk2(a1.w);
                ffma2(acc[28], av, b0.x); ffma2(acc[29], av, b0.y);
                ffma2(acc[30], av, b1.x); ffma2(acc[31], av, b1.y);
            }
        }

        // epilogue: d = (||x||^2 - 2 s) + ||e||^2 (jax op order)
        {
            const int cb = cbase + (nt << 7);
            const float4 e0 = *(const float4*)&g_enorm[cb + (tx << 2)];
            const float4 e1 = *(const float4*)&g_enorm[cb + 64 + (tx << 2)];
            const float en[8] = {e0.x, e0.y, e0.z, e0.w, e1.x, e1.y, e1.z, e1.w};
            const int c0 = cb + (tx << 2);
            const int cidx[8] = {c0, c0 + 1, c0 + 2, c0 + 3, c0 + 64, c0 + 65, c0 + 66, c0 + 67};
#pragma unroll
            for (int i = 0; i < 8; i++) {
                const float x2 = rn[i];
#pragma unroll
                for (int j = 0; j < 4; j++) {
                    const unsigned long long u = acc[i * 4 + j];
                    const float d0 = (x2 - 2.0f * f2lo(u)) + en[j * 2];
                    const float d1 = (x2 - 2.0f * f2hi(u)) + en[j * 2 + 1];
                    if (d0 < bestd[i]) { bestd[i] = d0; besti[i] = cidx[j * 2]; }
                    if (d1 < bestd[i]) { bestd[i] = d1; besti[i] = cidx[j * 2 + 1]; }
                }
            }
        }
    }

    // cross-thread argmin reduction, then global atomicMin merge
    float* rv = (float*)&As[0][0][0];
    int*   ri = (int*)&Bs[0][0][0];
    __syncthreads();
#pragma unroll
    for (int i = 0; i < 8; i++) {
        const int row = (i < 4) ? (ty << 2) + i : 64 + (ty << 2) + (i - 4);
        rv[row * 16 + tx] = bestd[i];
        ri[row * 16 + tx] = besti[i];
    }
    __syncthreads();
    if (tid < TM) {
        const int row = tid;
        float bv = rv[row * 16];
        int   bi = ri[row * 16];
#pragma unroll
        for (int t = 1; t < 16; t++) {
            const float v = rv[row * 16 + t];
            const int   ix = ri[row * 16 + t];
            if (v < bv || (v == bv && ix < bi)) { bv = v; bi = ix; }
        }
        const unsigned long long packed = ((unsigned long long)sortkey(bv) << 32) | (unsigned)bi;
        atomicMin(&g_best[rbase + row], packed);
    }
    (void)out;
}

// ---------------- gather: indices, usage, z_q, z_q_st ----------------
__global__ void gather_k(const float* __restrict__ emb, const float* __restrict__ ze,
                         float* __restrict__ out) {
    const int tid = threadIdx.x;
    const int rbase = blockIdx.x * 128;
    const int row = rbase + (tid >> 1);
    const int half = tid & 1;
    const int code = (int)(unsigned)g_best[row];
    if (half == 0) {
        out[OFF_IDX + row] = (float)code;
        atomicAdd(&g_usage[code], 1);
    }
    const float4* src = (const float4*)(emb + (size_t)code * DIM + half * 128);
    const float4* sze = (const float4*)(ze + (size_t)row * DIM + half * 128);
    float4* d1 = (float4*)(out + (size_t)row * DIM + half * 128);
    float4* d2 = (float4*)(out + OFF_ZQ + (size_t)row * DIM + half * 128);
#pragma unroll
    for (int q = 0; q < 32; q++) {
        const float4 v = src[q];
        const float4 x = sze[q];
        float4 st;
        st.x = x.x + (v.x - x.x);
        st.y = x.y + (v.y - x.y);
        st.z = x.z + (v.z - x.z);
        st.w = x.w + (v.w - x.w);
        d1[q] = st;
        d2[q] = v;
    }
}

// ---------------- stats ----------------
__global__ void stats_k(float* __restrict__ out) {
    __shared__ float se[256];
    __shared__ int   sd[256];
    const int t = threadIdx.x;
    float ent = 0.f;
    int dead = 0;
    for (int c = t; c < KCODES; c += 256) {
        const int u = g_usage[c];
        if (u == 0) dead++;
        else {
            const float p = (float)u * (1.0f / (float)NROWS);
            ent -= p * logf(p);
        }
    }
    se[t] = ent; sd[t] = dead;
    __syncthreads();
    for (int off = 128; off > 0; off >>= 1) {
        if (t < off) { se[t] += se[t + off]; sd[t] += sd[t + off]; }
        __syncthreads();
    }
    if (t == 0) {
        out[OFF_STATS]     = expf(se[0]);
        out[OFF_STATS + 1] = (float)sd[0] * (1.0f / (float)KCODES);
    }
}

// ---------------- launch ----------------
extern "C" void kernel_launch(void* const* d_in, const int* in_sizes, int n_in,
                              void* d_out, int out_size) {
    const float* z_e = (const float*)d_in[0];
    const float* emb = (const float*)d_in[1];
    if (n_in >= 2 && in_sizes[0] == KCODES * DIM && in_sizes[1] == NROWS * DIM) {
        const float* t = z_e; z_e = emb; emb = t;  // defensive input-order swap
    }
    float* out = (float*)d_out;

    transpose256_k<NROWS, false><<<dim3(NROWS / 32, DIM / 32), dim3(32, 8)>>>(z_e);
    transpose256_k<KCODES, true><<<dim3(KCODES / 32, DIM / 32), dim3(32, 8)>>>(emb);
    norms_k<<<NROWS / 256, 256>>>(z_e, emb);
    vq_main_k<<<(NROWS / TM) * 8, 256>>>(out);
    gather_k<<<NROWS / 128, 256>>>(emb, z_e, out);
    stats_k<<<1, 256>>>(out);
}